// round 15
// baseline (speedup 1.0000x reference)
#include <cuda_runtime.h>
#include <cuda_bf16.h>
#include <math.h>
#include <stdint.h>

#define B_   256
#define N_   300
#define T_   64
#define FIN  3
#define U_   256
#define G_   1024            // 4*U_
#define K0   900             // N_*FIN
#define K0P  960             // padded to multiple of 64
#define M_   16384           // B_*T_
#define FOUT 2
#define ND   600             // N_*FOUT

// ---------------- scratch (static device globals; no allocation) ----------------
__device__ __nv_bfloat16 g_ahi[(size_t)M_ * K0P];   // x transposed, bf16-hi
__device__ __nv_bfloat16 g_alo[(size_t)M_ * K0P];   // x transposed, bf16-lo
__device__ __nv_bfloat16 g_bhi[(size_t)G_ * K0P];   // weight K-major, bf16-hi (max size)
__device__ __nv_bfloat16 g_blo[(size_t)G_ * K0P];
__device__ __nv_bfloat16 g_uhi[(size_t)G_ * U_];    // recurrent U, permuted K-major, hi
__device__ __nv_bfloat16 g_ulo[(size_t)G_ * U_];
__device__ __nv_bfloat16 g_hhi[(size_t)M_ * U_];    // h sequence bf16-hi
__device__ __nv_bfloat16 g_hlo[(size_t)M_ * U_];    // h sequence bf16-lo
__device__ float    g_zx[(size_t)M_ * G_];          // gate pre-acts
__device__ unsigned g_bar[2][16];                   // per-(layer, batch-tile) counters

__global__ void reset_bar_kernel() {
    int i = threadIdx.x;
    if (i < 16) { g_bar[0][i] = 0u; g_bar[1][i] = 0u; }
}

// single dynamic-smem symbol for all kernels
extern __shared__ char dynsmem[];

// ---------------- bf16 2-term split ----------------
__device__ __forceinline__ void bf16split(float v, __nv_bfloat16& hi, __nv_bfloat16& lo) {
    hi = __float2bfloat16(v);
    lo = __float2bfloat16(v - __bfloat162float(hi));
}

// ---------------- coalesced input transpose + split ----------------
__global__ void transpose_x_kernel(const float* __restrict__ x) {
    __shared__ float tile[32][195];
    const int tid = threadIdx.x;
    const int b = blockIdx.y;
    const int n0 = blockIdx.x * 32;
    const float* xb = x + (size_t)b * N_ * T_ * FIN + (size_t)n0 * T_ * FIN;

    for (int idx = tid; idx < 32 * 192; idx += 256) {
        int nl = idx / 192, j = idx - nl * 192;
        float v = (n0 + nl < N_) ? xb[nl * 192 + j] : 0.f;
        tile[nl][j] = v;
    }
    __syncthreads();

    long rowbase = (long)b * T_;
    for (int idx = tid; idx < 64 * 96; idx += 256) {
        int t = idx / 96, cl = idx - t * 96;
        int nl = cl / 3, f = cl - nl * 3;
        float v = tile[nl][t * 3 + f];
        __nv_bfloat16 hi, lo;
        bf16split(v, hi, lo);
        long o = (rowbase + t) * K0P + n0 * 3 + cl;
        g_ahi[o] = hi;
        g_alo[o] = lo;
    }
}

// ---------------- weight transpose + split: W (K,N) -> (N, Ks) K-major hi/lo ----------------
__global__ void wtrans_kernel(const float* __restrict__ W, int K, int N, int Ks) {
    long i = (long)blockIdx.x * blockDim.x + threadIdx.x;
    if (i >= (long)N * Ks) return;
    int k = (int)(i % Ks);
    int n = (int)(i / Ks);
    float v = (k < K) ? W[(long)k * N + n] : 0.f;
    __nv_bfloat16 hi, lo;
    bf16split(v, hi, lo);
    g_bhi[i] = hi;
    g_blo[i] = lo;
}

// ---------------- recurrent-U permute + split ----------------
// permuted col cp -> (gate, unit): ublk=cp>>7, local=cp&127, warp_n=local>>4, c=local&15,
// gate=(c>>3)*2+(c&1), unit=ublk*32+warp_n*4+((c>>1)&3); orig col = gate*256+unit.
__global__ void utrans_kernel(const float* __restrict__ U) {
    long i = (long)blockIdx.x * blockDim.x + threadIdx.x;
    if (i >= (long)G_ * U_) return;
    int k  = (int)(i & 255);
    int cp = (int)(i >> 8);
    int ublk = cp >> 7;
    int local = cp & 127;
    int warp_n = local >> 4;
    int c = local & 15;
    int gate = ((c >> 3) << 1) | (c & 1);
    int unit = ublk * 32 + warp_n * 4 + ((c >> 1) & 3);
    float v = U[(long)k * G_ + gate * U_ + unit];
    __nv_bfloat16 hi, lo;
    bf16split(v, hi, lo);
    g_uhi[i] = hi;
    g_ulo[i] = lo;
}

// ================= mma.sync helpers =================
__device__ __forceinline__ uint32_t smem_u32(const void* p) {
    uint32_t a;
    asm("{ .reg .u64 t; cvta.to.shared.u64 t, %1; cvt.u32.u64 %0, t; }" : "=r"(a) : "l"(p));
    return a;
}
__device__ __forceinline__ uint32_t sw128(uint32_t o) { return o ^ ((o >> 3) & 0x70); }

__device__ __forceinline__ void ldsm_x4(uint32_t addr, uint32_t& r0, uint32_t& r1,
                                        uint32_t& r2, uint32_t& r3) {
    asm volatile("ldmatrix.sync.aligned.m8n8.x4.shared.b16 {%0,%1,%2,%3}, [%4];"
                 : "=r"(r0), "=r"(r1), "=r"(r2), "=r"(r3) : "r"(addr));
}

__device__ __forceinline__ void mma_bf16(float* d, const uint32_t* a, uint32_t b0, uint32_t b1) {
    asm volatile(
        "mma.sync.aligned.m16n8k16.row.col.f32.bf16.bf16.f32 "
        "{%0,%1,%2,%3}, {%4,%5,%6,%7}, {%8,%9}, {%0,%1,%2,%3};"
        : "+f"(d[0]), "+f"(d[1]), "+f"(d[2]), "+f"(d[3])
        : "r"(a[0]), "r"(a[1]), "r"(a[2]), "r"(a[3]), "r"(b0), "r"(b1));
}

__device__ __forceinline__ void cp_async16(uint32_t dst, const void* src, uint32_t src_bytes) {
    asm volatile("cp.async.cg.shared.global [%0], [%1], 16, %2;"
                 :: "r"(dst), "l"(src), "r"(src_bytes));
}

// ---------------- tensor-core GEMM (feed-forward): C = A @ B^T + bias ----------------
// 128x256 tile, warp tile 64x64 (8 warps = 2m x 4n), BK=64,
// 2-stage cp.async pipeline (2 x 96KB). LDSM:HMMA ratio 1:6 per k16.
#define ST_A_HI 0
#define ST_A_LO 16384
#define ST_B_HI 32768
#define ST_B_LO 65536
#define STAGE_SZ 98304
#define MM_SMEM  196608

template <bool SCATTER>
__global__ void __launch_bounds__(256, 1)
mma_gemm_kernel(const __nv_bfloat16* __restrict__ Ahi, const __nv_bfloat16* __restrict__ Alo,
                const __nv_bfloat16* __restrict__ Bhi, const __nv_bfloat16* __restrict__ Blo,
                const float* __restrict__ bias, float* __restrict__ C,
                int Ks, int N) {
    char* smem = dynsmem;
    const int tid  = threadIdx.x;
    const int lane = tid & 31;
    const int wid  = tid >> 5;
    const int warp_m = wid >> 2;       // 0..1 -> 64 rows
    const int warp_n = wid & 3;        // 0..3 -> 64 cols
    const int m0 = blockIdx.y * 128;
    const int n0 = blockIdx.x * 256;
    const uint32_t sbase = smem_u32(smem);

    float acc[4][8][4];
#pragma unroll
    for (int i = 0; i < 4; i++)
#pragma unroll
        for (int j = 0; j < 8; j++)
#pragma unroll
            for (int q = 0; q < 4; q++) acc[i][j][q] = 0.f;

    const int iters = Ks >> 6;

    auto load_stage = [&](int kt, int buf) {
        uint32_t bb = sbase + (uint32_t)buf * STAGE_SZ;
        // A: 128 rows x 8 chunks (hi+lo)
#pragma unroll
        for (int i = 0; i < 4; i++) {
            int idx = tid + i * 256;            // 0..1023
            int r = idx >> 3, kq = idx & 7;
            uint32_t so = sw128((uint32_t)(r * 128 + kq * 16));
            cp_async16(bb + ST_A_HI + so, Ahi + (size_t)(m0 + r) * Ks + kt + kq * 8, 16u);
            cp_async16(bb + ST_A_LO + so, Alo + (size_t)(m0 + r) * Ks + kt + kq * 8, 16u);
        }
        // B: 256 rows x 8 chunks (hi+lo)
#pragma unroll
        for (int i = 0; i < 8; i++) {
            int idx = tid + i * 256;            // 0..2047
            int r = idx >> 3, kq = idx & 7;
            uint32_t so = sw128((uint32_t)(r * 128 + kq * 16));
            uint32_t vbytes = (n0 + r < N) ? 16u : 0u;
            int rcl = (n0 + r < N) ? (n0 + r) : 0;
            cp_async16(bb + ST_B_HI + so, Bhi + (size_t)rcl * Ks + kt + kq * 8, vbytes);
            cp_async16(bb + ST_B_LO + so, Blo + (size_t)rcl * Ks + kt + kq * 8, vbytes);
        }
        asm volatile("cp.async.commit_group;" ::: "memory");
    };

    load_stage(0, 0);

    for (int it = 0; it < iters; it++) {
        if (it + 1 < iters) {
            load_stage((it + 1) << 6, (it + 1) & 1);
            asm volatile("cp.async.wait_group 1;" ::: "memory");
        } else {
            asm volatile("cp.async.wait_group 0;" ::: "memory");
        }
        __syncthreads();

        uint32_t bb = sbase + (uint32_t)(it & 1) * STAGE_SZ;
#pragma unroll
        for (int ks = 0; ks < 4; ks++) {
            const int kb = ks * 16;
            // B fragments: 4 n16-groups x (hi,lo)
            uint32_t bh[4][4], bl[4][4];
#pragma unroll
            for (int ng = 0; ng < 4; ng++) {
                int nrow = warp_n * 64 + ng * 16 + (lane & 7) + (lane >> 4) * 8;
                int koff = kb + ((lane >> 3) & 1) * 8;
                uint32_t so = sw128((uint32_t)(nrow * 128 + koff * 2));
                ldsm_x4(bb + ST_B_HI + so, bh[ng][0], bh[ng][1], bh[ng][2], bh[ng][3]);
                ldsm_x4(bb + ST_B_LO + so, bl[ng][0], bl[ng][1], bl[ng][2], bl[ng][3]);
            }
#pragma unroll
            for (int mf = 0; mf < 4; mf++) {
                int mrow = warp_m * 64 + mf * 16 + (lane & 7) + ((lane >> 3) & 1) * 8;
                int koff = kb + (lane >> 4) * 8;
                uint32_t so = sw128((uint32_t)(mrow * 128 + koff * 2));
                uint32_t ah[4], al[4];
                ldsm_x4(bb + ST_A_HI + so, ah[0], ah[1], ah[2], ah[3]);
                ldsm_x4(bb + ST_A_LO + so, al[0], al[1], al[2], al[3]);
#pragma unroll
                for (int ng = 0; ng < 4; ng++) {
#pragma unroll
                    for (int h = 0; h < 2; h++) {
                        int nf = ng * 2 + h;
                        mma_bf16(acc[mf][nf], ah, bh[ng][h * 2], bh[ng][h * 2 + 1]);
                        mma_bf16(acc[mf][nf], ah, bl[ng][h * 2], bl[ng][h * 2 + 1]);
                        mma_bf16(acc[mf][nf], al, bh[ng][h * 2], bh[ng][h * 2 + 1]);
                    }
                }
            }
        }
        __syncthreads();
    }

    const int g  = lane >> 2;
    const int tq = lane & 3;
#pragma unroll
    for (int mf = 0; mf < 4; mf++) {
#pragma unroll
        for (int nf = 0; nf < 8; nf++) {
            int c = n0 + warp_n * 64 + nf * 8 + tq * 2;
            if (c >= N) continue;
            float bx = bias[c], by = bias[c + 1];
#pragma unroll
            for (int half = 0; half < 2; half++) {
                int m = m0 + warp_m * 64 + mf * 16 + g + half * 8;
                float vx = acc[mf][nf][half * 2 + 0] + bx;
                float vy = acc[mf][nf][half * 2 + 1] + by;
                if (SCATTER) {
                    int b = m >> 6, t = m & 63;
                    int nn = c >> 1;
                    float2* p = (float2*)&C[(((long)b * N_ + nn) * T_ + t) * FOUT];
                    *p = make_float2(vx, vy);
                } else {
                    *(float2*)&C[(size_t)m * N + c] = make_float2(vx, vy);
                }
            }
        }
    }
}

// ---------------- tensor-core persistent LSTM layer kernel (N-split, 8 warps) ------------
// (champion, unchanged) 128 blocks = 16 batch-tiles x 8 unit-tiles.
#define SM_U_HI  0                    // 4 panels x 16KB
#define SM_U_LO  65536
#define SM_H_HI  131072               // 4 panels x 2KB
#define SM_H_LO  139264
#define LSTM_SMEM 147456

__global__ void __launch_bounds__(256, 1)
lstm_kernel(const float* __restrict__ zx,   // (M_,1024) rows b*T+t, cols gate*256+unit
            const __nv_bfloat16* __restrict__ Uphi,  // permuted (1024,256) K-major
            const __nv_bfloat16* __restrict__ Uplo,
            __nv_bfloat16* __restrict__ hhi,         // (M_,256) rows b*T+t
            __nv_bfloat16* __restrict__ hlo,
            int bar_idx) {
    char* smem = dynsmem;
    const uint32_t sbase = smem_u32(smem);
    const int tid  = threadIdx.x;
    const int lane = tid & 31;
    const int warp_n = tid >> 5;            // 0..7, 16 permuted cols each
    const int ublk = blockIdx.x & 7;
    const int bblk = blockIdx.x >> 3;
    const int b0 = bblk * 16;
    const int cbase = ublk * 128;           // permuted col base

    // ---- load U slice into smem panels (once): 128 rows x 256 k, hi+lo ----
    for (int idx = tid; idx < 4096; idx += 256) {
        int n = idx >> 5, kq = idx & 31;
        int k = kq * 8;
        int p = k >> 6, ko = k & 63;
        uint32_t dst = (uint32_t)(p * 16384) + sw128((uint32_t)(n * 128 + ko * 2));
        *(uint4*)(smem + SM_U_HI + dst) = *(const uint4*)(Uphi + (size_t)(cbase + n) * U_ + k);
        *(uint4*)(smem + SM_U_LO + dst) = *(const uint4*)(Uplo + (size_t)(cbase + n) * U_ + k);
    }
    __syncthreads();

    const int g  = lane >> 2;               // row group 0..7
    const int tq = lane & 3;
    const int uglob = ublk * 32 + warp_n * 4 + tq;   // this thread's unit

    unsigned* bar = &g_bar[bar_idx][bblk];

    float cst[2] = {0.f, 0.f};               // rows g, g+8
    float zq[4][2];                          // [gate][row half]

    // prefetch zx for t=0
#pragma unroll
    for (int half = 0; half < 2; half++) {
        long row = (long)(b0 + half * 8 + g) * T_ + 0;
#pragma unroll
        for (int gt = 0; gt < 4; gt++)
            zq[gt][half] = zx[row * G_ + gt * U_ + uglob];
    }

    for (int t = 0; t < T_; t++) {
        float acc[2][4];                     // [nf][quad]
#pragma unroll
        for (int nf = 0; nf < 2; nf++)
#pragma unroll
            for (int q = 0; q < 4; q++) acc[nf][q] = 0.f;

        if (t > 0) {
            // stage h_{t-1} tile: 16 rows x 256 k, hi+lo
#pragma unroll
            for (int j = 0; j < 2; j++) {
                int idx = tid + j * 256;         // 0..511
                int r = idx >> 5, kq = idx & 31;
                int k = kq * 8;
                int p = k >> 6, ko = k & 63;
                long src = ((long)(b0 + r) * T_ + (t - 1)) * U_ + k;
                uint32_t dst = (uint32_t)(p * 2048) + sw128((uint32_t)(r * 128 + ko * 2));
                *(uint4*)(smem + SM_H_HI + dst) = *(const uint4*)(hhi + src);
                *(uint4*)(smem + SM_H_LO + dst) = *(const uint4*)(hlo + src);
            }
            __syncthreads();

            // 16 k-chunks: A x4 pair + B x4 pair + 6 HMMA each
#pragma unroll
            for (int kc = 0; kc < 16; kc++) {
                const int p = kc >> 2;
                const int kb = (kc & 3) * 16;
                int mrow = (lane & 7) + ((lane >> 3) & 1) * 8;
                int koffA = kb + (lane >> 4) * 8;
                uint32_t soA = (uint32_t)(p * 2048) + sw128((uint32_t)(mrow * 128 + koffA * 2));
                uint32_t ah[4], al[4];
                ldsm_x4(sbase + SM_H_HI + soA, ah[0], ah[1], ah[2], ah[3]);
                ldsm_x4(sbase + SM_H_LO + soA, al[0], al[1], al[2], al[3]);
                int nrow = warp_n * 16 + (lane & 7) + (lane >> 4) * 8;
                int koffB = kb + ((lane >> 3) & 1) * 8;
                uint32_t soB = (uint32_t)(p * 16384) + sw128((uint32_t)(nrow * 128 + koffB * 2));
                uint32_t bh[4], bl[4];
                ldsm_x4(sbase + SM_U_HI + soB, bh[0], bh[1], bh[2], bh[3]);
                ldsm_x4(sbase + SM_U_LO + soB, bl[0], bl[1], bl[2], bl[3]);
#pragma unroll
                for (int nf = 0; nf < 2; nf++) {
                    mma_bf16(acc[nf], ah, bh[nf * 2], bh[nf * 2 + 1]);
                    mma_bf16(acc[nf], ah, bl[nf * 2], bl[nf * 2 + 1]);
                    mma_bf16(acc[nf], al, bh[nf * 2], bh[nf * 2 + 1]);
                }
            }
        }

        // gates + state update + bf16 h store
        // thread cols: nf=0 -> (gate i, gate f), nf=1 -> (gate g, gate o) of unit uglob
#pragma unroll
        for (int half = 0; half < 2; half++) {
            long row = (long)(b0 + half * 8 + g) * T_ + t;
            float ig = 1.f / (1.f + expf(-(zq[0][half] + acc[0][half * 2 + 0])));
            float fg = 1.f / (1.f + expf(-(zq[1][half] + acc[0][half * 2 + 1])));
            float gg = fmaxf(zq[2][half] + acc[1][half * 2 + 0], 0.f);
            float og = 1.f / (1.f + expf(-(zq[3][half] + acc[1][half * 2 + 1])));
            float c  = fg * cst[half] + ig * gg;
            cst[half] = c;
            float h = og * fmaxf(c, 0.f);
            __nv_bfloat16 phi, plo;
            bf16split(h, phi, plo);
            hhi[row * U_ + uglob] = phi;
            hlo[row * U_ + uglob] = plo;
        }

        if (t < T_ - 1) {
            // prefetch zx for t+1 (overlaps with barrier wait)
#pragma unroll
            for (int half = 0; half < 2; half++) {
                long row = (long)(b0 + half * 8 + g) * T_ + (t + 1);
#pragma unroll
                for (int gt = 0; gt < 4; gt++)
                    zq[gt][half] = zx[row * G_ + gt * U_ + uglob];
            }
            // per-batch-tile barrier: release-add, acquire-poll (no membar.gpu)
            __syncthreads();
            if (tid == 0) {
                asm volatile("red.release.gpu.global.add.u32 [%0], 1;" :: "l"(bar) : "memory");
                unsigned target = 8u * (unsigned)(t + 1);
                unsigned v;
                do {
                    asm volatile("ld.acquire.gpu.global.u32 %0, [%1];" : "=r"(v) : "l"(bar) : "memory");
                } while (v < target);
            }
            __syncthreads();
        }
    }
}

// ---------------- host launcher ----------------
extern "C" void kernel_launch(void* const* d_in, const int* in_sizes, int n_in,
                              void* d_out, int out_size) {
    const float* x  = (const float*)d_in[0];
    const float* W0 = (const float*)d_in[1];
    const float* U0 = (const float*)d_in[2];
    const float* b0 = (const float*)d_in[3];
    const float* W1 = (const float*)d_in[4];
    const float* U1 = (const float*)d_in[5];
    const float* b1 = (const float*)d_in[6];
    const float* Wd = (const float*)d_in[7];
    const float* bd = (const float*)d_in[8];
    float* out = (float*)d_out;

    __nv_bfloat16 *ahi, *alo, *bhi, *blo, *uhi, *ulo, *hhi, *hlo;
    float *zx_p;
    cudaGetSymbolAddress((void**)&ahi, g_ahi);
    cudaGetSymbolAddress((void**)&alo, g_alo);
    cudaGetSymbolAddress((void**)&bhi, g_bhi);
    cudaGetSymbolAddress((void**)&blo, g_blo);
    cudaGetSymbolAddress((void**)&uhi, g_uhi);
    cudaGetSymbolAddress((void**)&ulo, g_ulo);
    cudaGetSymbolAddress((void**)&hhi, g_hhi);
    cudaGetSymbolAddress((void**)&hlo, g_hlo);
    cudaGetSymbolAddress((void**)&zx_p, g_zx);

    cudaFuncSetAttribute(lstm_kernel, cudaFuncAttributeMaxDynamicSharedMemorySize, LSTM_SMEM);
    cudaFuncSetAttribute(mma_gemm_kernel<false>, cudaFuncAttributeMaxDynamicSharedMemorySize, MM_SMEM);
    cudaFuncSetAttribute(mma_gemm_kernel<true>,  cudaFuncAttributeMaxDynamicSharedMemorySize, MM_SMEM);

    reset_bar_kernel<<<1, 32>>>();

    // x -> (B*T, 960) bf16 hi/lo (coalesced tiled transpose)
    transpose_x_kernel<<<dim3(10, B_), 256>>>(x);

    // W0 -> (1024, 960) K-major hi/lo ; U0 -> permuted
    {
        long total = (long)G_ * K0P;
        wtrans_kernel<<<(int)((total + 255) / 256), 256>>>(W0, K0, G_, K0P);
        long tu = (long)G_ * U_;
        utrans_kernel<<<(int)((tu + 255) / 256), 256>>>(U0);
    }
    // zx = x @ W0 + b0
    mma_gemm_kernel<false><<<dim3(G_ / 256, M_ / 128), 256, MM_SMEM>>>(
        ahi, alo, bhi, blo, b0, zx_p, K0P, G_);

    // LSTM layer 0 -> hhi/hlo
    lstm_kernel<<<128, 256, LSTM_SMEM>>>(zx_p, uhi, ulo, hhi, hlo, 0);

    // W1 -> (1024, 256) K-major hi/lo ; U1 -> permuted
    {
        long total = (long)G_ * U_;
        wtrans_kernel<<<(int)((total + 255) / 256), 256>>>(W1, U_, G_, U_);
        utrans_kernel<<<(int)((total + 255) / 256), 256>>>(U1);
    }
    // zx = h0 @ W1 + b1
    mma_gemm_kernel<false><<<dim3(G_ / 256, M_ / 128), 256, MM_SMEM>>>(
        hhi, hlo, bhi, blo, b1, zx_p, U_, G_);

    // LSTM layer 1 -> hhi/hlo
    lstm_kernel<<<128, 256, LSTM_SMEM>>>(zx_p, uhi, ulo, hhi, hlo, 1);

    // Wd -> (600, 256) K-major hi/lo
    {
        long total = (long)ND * U_;
        wtrans_kernel<<<(int)((total + 255) / 256), 256>>>(Wd, U_, ND, U_);
    }
    // out = h1 @ Wd + bd, scattered to (B, N, T, 2)
    mma_gemm_kernel<true><<<dim3((ND + 255) / 256, M_ / 128), 256, MM_SMEM>>>(
        hhi, hlo, bhi, blo, bd, out, U_, ND);
}

// round 16
// speedup vs baseline: 1.0505x; 1.0505x over previous
#include <cuda_runtime.h>
#include <cuda_bf16.h>
#include <math.h>
#include <stdint.h>

#define B_   256
#define N_   300
#define T_   64
#define FIN  3
#define U_   256
#define G_   1024            // 4*U_
#define K0   900             // N_*FIN
#define K0P  960             // padded to multiple of 64
#define M_   16384           // B_*T_
#define FOUT 2
#define ND   600             // N_*FOUT

// ---------------- scratch (static device globals; no allocation) ----------------
__device__ __nv_bfloat16 g_ahi[(size_t)M_ * K0P];   // x transposed, bf16-hi
__device__ __nv_bfloat16 g_alo[(size_t)M_ * K0P];   // x transposed, bf16-lo
__device__ __nv_bfloat16 g_bhi[(size_t)G_ * K0P];   // weight K-major, bf16-hi (max size)
__device__ __nv_bfloat16 g_blo[(size_t)G_ * K0P];
__device__ __nv_bfloat16 g_uhi[(size_t)G_ * U_];    // recurrent U, permuted K-major, hi
__device__ __nv_bfloat16 g_ulo[(size_t)G_ * U_];
__device__ __nv_bfloat16 g_hhi[(size_t)M_ * U_];    // h sequence bf16-hi
__device__ __nv_bfloat16 g_hlo[(size_t)M_ * U_];    // h sequence bf16-lo
__device__ float    g_zx[(size_t)M_ * G_];          // gate pre-acts
__device__ unsigned g_bar[2][16];                   // per-(layer, batch-tile) counters

__global__ void reset_bar_kernel() {
    int i = threadIdx.x;
    if (i < 16) { g_bar[0][i] = 0u; g_bar[1][i] = 0u; }
}

// single dynamic-smem symbol for all kernels
extern __shared__ char dynsmem[];

// ---------------- bf16 2-term split ----------------
__device__ __forceinline__ void bf16split(float v, __nv_bfloat16& hi, __nv_bfloat16& lo) {
    hi = __float2bfloat16(v);
    lo = __float2bfloat16(v - __bfloat162float(hi));
}

// fast sigmoid via MUFU.EX2 path
__device__ __forceinline__ float fsigmoid(float x) {
    return 1.f / (1.f + __expf(-x));
}

// ---------------- coalesced input transpose + split ----------------
__global__ void transpose_x_kernel(const float* __restrict__ x) {
    __shared__ float tile[32][195];
    const int tid = threadIdx.x;
    const int b = blockIdx.y;
    const int n0 = blockIdx.x * 32;
    const float* xb = x + (size_t)b * N_ * T_ * FIN + (size_t)n0 * T_ * FIN;

    for (int idx = tid; idx < 32 * 192; idx += 256) {
        int nl = idx / 192, j = idx - nl * 192;
        float v = (n0 + nl < N_) ? xb[nl * 192 + j] : 0.f;
        tile[nl][j] = v;
    }
    __syncthreads();

    long rowbase = (long)b * T_;
    for (int idx = tid; idx < 64 * 96; idx += 256) {
        int t = idx / 96, cl = idx - t * 96;
        int nl = cl / 3, f = cl - nl * 3;
        float v = tile[nl][t * 3 + f];
        __nv_bfloat16 hi, lo;
        bf16split(v, hi, lo);
        long o = (rowbase + t) * K0P + n0 * 3 + cl;
        g_ahi[o] = hi;
        g_alo[o] = lo;
    }
}

// ---------------- weight transpose + split: W (K,N) -> (N, Ks) K-major hi/lo ----------------
__global__ void wtrans_kernel(const float* __restrict__ W, int K, int N, int Ks) {
    long i = (long)blockIdx.x * blockDim.x + threadIdx.x;
    if (i >= (long)N * Ks) return;
    int k = (int)(i % Ks);
    int n = (int)(i / Ks);
    float v = (k < K) ? W[(long)k * N + n] : 0.f;
    __nv_bfloat16 hi, lo;
    bf16split(v, hi, lo);
    g_bhi[i] = hi;
    g_blo[i] = lo;
}

// ---------------- recurrent-U permute + split ----------------
// permuted col cp -> (gate, unit): ublk=cp>>7, local=cp&127, warp_n=local>>4, c=local&15,
// gate=(c>>3)*2+(c&1), unit=ublk*32+warp_n*4+((c>>1)&3); orig col = gate*256+unit.
__global__ void utrans_kernel(const float* __restrict__ U) {
    long i = (long)blockIdx.x * blockDim.x + threadIdx.x;
    if (i >= (long)G_ * U_) return;
    int k  = (int)(i & 255);
    int cp = (int)(i >> 8);
    int ublk = cp >> 7;
    int local = cp & 127;
    int warp_n = local >> 4;
    int c = local & 15;
    int gate = ((c >> 3) << 1) | (c & 1);
    int unit = ublk * 32 + warp_n * 4 + ((c >> 1) & 3);
    float v = U[(long)k * G_ + gate * U_ + unit];
    __nv_bfloat16 hi, lo;
    bf16split(v, hi, lo);
    g_uhi[i] = hi;
    g_ulo[i] = lo;
}

// ================= mma.sync helpers =================
__device__ __forceinline__ uint32_t smem_u32(const void* p) {
    uint32_t a;
    asm("{ .reg .u64 t; cvta.to.shared.u64 t, %1; cvt.u32.u64 %0, t; }" : "=r"(a) : "l"(p));
    return a;
}
__device__ __forceinline__ uint32_t sw128(uint32_t o) { return o ^ ((o >> 3) & 0x70); }

__device__ __forceinline__ void ldsm_x4(uint32_t addr, uint32_t& r0, uint32_t& r1,
                                        uint32_t& r2, uint32_t& r3) {
    asm volatile("ldmatrix.sync.aligned.m8n8.x4.shared.b16 {%0,%1,%2,%3}, [%4];"
                 : "=r"(r0), "=r"(r1), "=r"(r2), "=r"(r3) : "r"(addr));
}

__device__ __forceinline__ void mma_bf16(float* d, const uint32_t* a, uint32_t b0, uint32_t b1) {
    asm volatile(
        "mma.sync.aligned.m16n8k16.row.col.f32.bf16.bf16.f32 "
        "{%0,%1,%2,%3}, {%4,%5,%6,%7}, {%8,%9}, {%0,%1,%2,%3};"
        : "+f"(d[0]), "+f"(d[1]), "+f"(d[2]), "+f"(d[3])
        : "r"(a[0]), "r"(a[1]), "r"(a[2]), "r"(a[3]), "r"(b0), "r"(b1));
}

__device__ __forceinline__ void cp_async16(uint32_t dst, const void* src, uint32_t src_bytes) {
    asm volatile("cp.async.cg.shared.global [%0], [%1], 16, %2;"
                 :: "r"(dst), "l"(src), "r"(src_bytes));
}

// ---------------- tensor-core GEMM (feed-forward): C = A @ B^T + bias ----------------
// 128x128 tile, BK=64, 256 threads, double-buffered cp.async (2 x 64KB stages).
#define ST_A_HI 0
#define ST_A_LO 16384
#define ST_B_HI 32768
#define ST_B_LO 49152
#define STAGE_SZ 65536
#define MM_SMEM  131072

template <bool SCATTER>
__global__ void __launch_bounds__(256, 1)
mma_gemm_kernel(const __nv_bfloat16* __restrict__ Ahi, const __nv_bfloat16* __restrict__ Alo,
                const __nv_bfloat16* __restrict__ Bhi, const __nv_bfloat16* __restrict__ Blo,
                const float* __restrict__ bias, float* __restrict__ C,
                int Ks, int N) {
    char* smem = dynsmem;
    const int tid  = threadIdx.x;
    const int lane = tid & 31;
    const int wid  = tid >> 5;
    const int warp_m = wid >> 2;
    const int warp_n = wid & 3;
    const int m0 = blockIdx.y * 128;
    const int n0 = blockIdx.x * 128;
    const uint32_t sbase = smem_u32(smem);

    float acc[4][4][4];
#pragma unroll
    for (int i = 0; i < 4; i++)
#pragma unroll
        for (int j = 0; j < 4; j++)
#pragma unroll
            for (int q = 0; q < 4; q++) acc[i][j][q] = 0.f;

    const int iters = Ks >> 6;

    auto load_stage = [&](int kt, int buf) {
        uint32_t bb = sbase + (uint32_t)buf * STAGE_SZ;
#pragma unroll
        for (int i = 0; i < 4; i++) {
            int idx = tid + i * 256;
            int r = idx >> 3, kq = idx & 7;
            uint32_t so = sw128((uint32_t)(r * 128 + kq * 16));
            cp_async16(bb + ST_A_HI + so, Ahi + (size_t)(m0 + r) * Ks + kt + kq * 8, 16u);
            cp_async16(bb + ST_A_LO + so, Alo + (size_t)(m0 + r) * Ks + kt + kq * 8, 16u);
            uint32_t vbytes = (n0 + r < N) ? 16u : 0u;
            int rcl = (n0 + r < N) ? (n0 + r) : 0;
            cp_async16(bb + ST_B_HI + so, Bhi + (size_t)rcl * Ks + kt + kq * 8, vbytes);
            cp_async16(bb + ST_B_LO + so, Blo + (size_t)rcl * Ks + kt + kq * 8, vbytes);
        }
        asm volatile("cp.async.commit_group;" ::: "memory");
    };

    load_stage(0, 0);

    for (int it = 0; it < iters; it++) {
        if (it + 1 < iters) {
            load_stage((it + 1) << 6, (it + 1) & 1);
            asm volatile("cp.async.wait_group 1;" ::: "memory");
        } else {
            asm volatile("cp.async.wait_group 0;" ::: "memory");
        }
        __syncthreads();

        uint32_t bb = sbase + (uint32_t)(it & 1) * STAGE_SZ;
#pragma unroll
        for (int ks = 0; ks < 4; ks++) {
            const int kb = ks * 16;
            uint32_t bh[2][4], bl[2][4];
#pragma unroll
            for (int ng = 0; ng < 2; ng++) {
                int nrow = warp_n * 32 + ng * 16 + (lane & 7) + (lane >> 4) * 8;
                int koff = kb + ((lane >> 3) & 1) * 8;
                uint32_t so = sw128((uint32_t)(nrow * 128 + koff * 2));
                ldsm_x4(bb + ST_B_HI + so, bh[ng][0], bh[ng][1], bh[ng][2], bh[ng][3]);
                ldsm_x4(bb + ST_B_LO + so, bl[ng][0], bl[ng][1], bl[ng][2], bl[ng][3]);
            }
#pragma unroll
            for (int mf = 0; mf < 4; mf++) {
                int mrow = warp_m * 64 + mf * 16 + (lane & 7) + ((lane >> 3) & 1) * 8;
                int koff = kb + (lane >> 4) * 8;
                uint32_t so = sw128((uint32_t)(mrow * 128 + koff * 2));
                uint32_t ah[4], al[4];
                ldsm_x4(bb + ST_A_HI + so, ah[0], ah[1], ah[2], ah[3]);
                ldsm_x4(bb + ST_A_LO + so, al[0], al[1], al[2], al[3]);
#pragma unroll
                for (int ng = 0; ng < 2; ng++) {
#pragma unroll
                    for (int h = 0; h < 2; h++) {
                        int nf = ng * 2 + h;
                        mma_bf16(acc[mf][nf], ah, bh[ng][h * 2], bh[ng][h * 2 + 1]);
                        mma_bf16(acc[mf][nf], ah, bl[ng][h * 2], bl[ng][h * 2 + 1]);
                        mma_bf16(acc[mf][nf], al, bh[ng][h * 2], bh[ng][h * 2 + 1]);
                    }
                }
            }
        }
        __syncthreads();
    }

    const int g  = lane >> 2;
    const int tq = lane & 3;
#pragma unroll
    for (int mf = 0; mf < 4; mf++) {
#pragma unroll
        for (int nf = 0; nf < 4; nf++) {
            int c = n0 + warp_n * 32 + nf * 8 + tq * 2;
            if (c >= N) continue;
            float bx = bias[c], by = bias[c + 1];
#pragma unroll
            for (int half = 0; half < 2; half++) {
                int m = m0 + warp_m * 64 + mf * 16 + g + half * 8;
                float vx = acc[mf][nf][half * 2 + 0] + bx;
                float vy = acc[mf][nf][half * 2 + 1] + by;
                if (SCATTER) {
                    int b = m >> 6, t = m & 63;
                    int nn = c >> 1;
                    float2* p = (float2*)&C[(((long)b * N_ + nn) * T_ + t) * FOUT];
                    *p = make_float2(vx, vy);
                } else {
                    *(float2*)&C[(size_t)m * N + c] = make_float2(vx, vy);
                }
            }
        }
    }
}

// ---------------- tensor-core persistent LSTM layer kernel (N-split, 8 warps) ------------
// 128 blocks = 16 batch-tiles x 8 unit-tiles. 256 threads = 8 warps x 16 permuted cols.
// 96 HMMA/warp/step; gates thread-local (__expf sigmoid); cp.async h staging;
// scoped per-batch-tile release/acquire barrier.
#define SM_U_HI  0                    // 4 panels x 16KB
#define SM_U_LO  65536
#define SM_H_HI  131072               // 4 panels x 2KB
#define SM_H_LO  139264
#define LSTM_SMEM 147456

__global__ void __launch_bounds__(256, 1)
lstm_kernel(const float* __restrict__ zx,   // (M_,1024) rows b*T+t, cols gate*256+unit
            const __nv_bfloat16* __restrict__ Uphi,  // permuted (1024,256) K-major
            const __nv_bfloat16* __restrict__ Uplo,
            __nv_bfloat16* __restrict__ hhi,         // (M_,256) rows b*T+t
            __nv_bfloat16* __restrict__ hlo,
            int bar_idx) {
    char* smem = dynsmem;
    const uint32_t sbase = smem_u32(smem);
    const int tid  = threadIdx.x;
    const int lane = tid & 31;
    const int warp_n = tid >> 5;            // 0..7, 16 permuted cols each
    const int ublk = blockIdx.x & 7;
    const int bblk = blockIdx.x >> 3;
    const int b0 = bblk * 16;
    const int cbase = ublk * 128;           // permuted col base

    // ---- load U slice into smem panels (once): 128 rows x 256 k, hi+lo ----
    for (int idx = tid; idx < 4096; idx += 256) {
        int n = idx >> 5, kq = idx & 31;
        int k = kq * 8;
        int p = k >> 6, ko = k & 63;
        uint32_t dst = (uint32_t)(p * 16384) + sw128((uint32_t)(n * 128 + ko * 2));
        *(uint4*)(smem + SM_U_HI + dst) = *(const uint4*)(Uphi + (size_t)(cbase + n) * U_ + k);
        *(uint4*)(smem + SM_U_LO + dst) = *(const uint4*)(Uplo + (size_t)(cbase + n) * U_ + k);
    }
    __syncthreads();

    const int g  = lane >> 2;               // row group 0..7
    const int tq = lane & 3;
    const int uglob = ublk * 32 + warp_n * 4 + tq;   // this thread's unit

    unsigned* bar = &g_bar[bar_idx][bblk];

    float cst[2] = {0.f, 0.f};               // rows g, g+8
    float zq[4][2];                          // [gate][row half]

    // prefetch zx for t=0
#pragma unroll
    for (int half = 0; half < 2; half++) {
        long row = (long)(b0 + half * 8 + g) * T_ + 0;
#pragma unroll
        for (int gt = 0; gt < 4; gt++)
            zq[gt][half] = zx[row * G_ + gt * U_ + uglob];
    }

    for (int t = 0; t < T_; t++) {
        float acc[2][4];                     // [nf][quad]
#pragma unroll
        for (int nf = 0; nf < 2; nf++)
#pragma unroll
            for (int q = 0; q < 4; q++) acc[nf][q] = 0.f;

        if (t > 0) {
            // stage h_{t-1} tile via cp.async: 16 rows x 256 k, hi+lo
#pragma unroll
            for (int j = 0; j < 2; j++) {
                int idx = tid + j * 256;         // 0..511
                int r = idx >> 5, kq = idx & 31;
                int k = kq * 8;
                int p = k >> 6, ko = k & 63;
                long src = ((long)(b0 + r) * T_ + (t - 1)) * U_ + k;
                uint32_t dst = (uint32_t)(p * 2048) + sw128((uint32_t)(r * 128 + ko * 2));
                cp_async16(sbase + SM_H_HI + dst, hhi + src, 16u);
                cp_async16(sbase + SM_H_LO + dst, hlo + src, 16u);
            }
            asm volatile("cp.async.commit_group;" ::: "memory");
            asm volatile("cp.async.wait_group 0;" ::: "memory");
            __syncthreads();

            // 16 k-chunks: A x4 pair + B x4 pair + 6 HMMA each
#pragma unroll
            for (int kc = 0; kc < 16; kc++) {
                const int p = kc >> 2;
                const int kb = (kc & 3) * 16;
                int mrow = (lane & 7) + ((lane >> 3) & 1) * 8;
                int koffA = kb + (lane >> 4) * 8;
                uint32_t soA = (uint32_t)(p * 2048) + sw128((uint32_t)(mrow * 128 + koffA * 2));
                uint32_t ah[4], al[4];
                ldsm_x4(sbase + SM_H_HI + soA, ah[0], ah[1], ah[2], ah[3]);
                ldsm_x4(sbase + SM_H_LO + soA, al[0], al[1], al[2], al[3]);
                int nrow = warp_n * 16 + (lane & 7) + (lane >> 4) * 8;
                int koffB = kb + ((lane >> 3) & 1) * 8;
                uint32_t soB = (uint32_t)(p * 16384) + sw128((uint32_t)(nrow * 128 + koffB * 2));
                uint32_t bh[4], bl[4];
                ldsm_x4(sbase + SM_U_HI + soB, bh[0], bh[1], bh[2], bh[3]);
                ldsm_x4(sbase + SM_U_LO + soB, bl[0], bl[1], bl[2], bl[3]);
#pragma unroll
                for (int nf = 0; nf < 2; nf++) {
                    mma_bf16(acc[nf], ah, bh[nf * 2], bh[nf * 2 + 1]);
                    mma_bf16(acc[nf], ah, bl[nf * 2], bl[nf * 2 + 1]);
                    mma_bf16(acc[nf], al, bh[nf * 2], bh[nf * 2 + 1]);
                }
            }
        }

        // gates (fast sigmoid) + state update + bf16 h store
        // thread cols: nf=0 -> (gate i, gate f), nf=1 -> (gate g, gate o) of unit uglob
#pragma unroll
        for (int half = 0; half < 2; half++) {
            long row = (long)(b0 + half * 8 + g) * T_ + t;
            float ig = fsigmoid(zq[0][half] + acc[0][half * 2 + 0]);
            float fg = fsigmoid(zq[1][half] + acc[0][half * 2 + 1]);
            float gg = fmaxf(zq[2][half] + acc[1][half * 2 + 0], 0.f);
            float og = fsigmoid(zq[3][half] + acc[1][half * 2 + 1]);
            float c  = fg * cst[half] + ig * gg;
            cst[half] = c;
            float h = og * fmaxf(c, 0.f);
            __nv_bfloat16 phi, plo;
            bf16split(h, phi, plo);
            hhi[row * U_ + uglob] = phi;
            hlo[row * U_ + uglob] = plo;
        }

        if (t < T_ - 1) {
            // prefetch zx for t+1 (overlaps with barrier wait)
#pragma unroll
            for (int half = 0; half < 2; half++) {
                long row = (long)(b0 + half * 8 + g) * T_ + (t + 1);
#pragma unroll
                for (int gt = 0; gt < 4; gt++)
                    zq[gt][half] = zx[row * G_ + gt * U_ + uglob];
            }
            // per-batch-tile barrier: release-add, acquire-poll
            __syncthreads();
            if (tid == 0) {
                asm volatile("red.release.gpu.global.add.u32 [%0], 1;" :: "l"(bar) : "memory");
                unsigned target = 8u * (unsigned)(t + 1);
                unsigned v;
                do {
                    asm volatile("ld.acquire.gpu.global.u32 %0, [%1];" : "=r"(v) : "l"(bar) : "memory");
                } while (v < target);
            }
            __syncthreads();
        }
    }
}

// ---------------- host launcher ----------------
extern "C" void kernel_launch(void* const* d_in, const int* in_sizes, int n_in,
                              void* d_out, int out_size) {
    const float* x  = (const float*)d_in[0];
    const float* W0 = (const float*)d_in[1];
    const float* U0 = (const float*)d_in[2];
    const float* b0 = (const float*)d_in[3];
    const float* W1 = (const float*)d_in[4];
    const float* U1 = (const float*)d_in[5];
    const float* b1 = (const float*)d_in[6];
    const float* Wd = (const float*)d_in[7];
    const float* bd = (const float*)d_in[8];
    float* out = (float*)d_out;

    __nv_bfloat16 *ahi, *alo, *bhi, *blo, *uhi, *ulo, *hhi, *hlo;
    float *zx_p;
    cudaGetSymbolAddress((void**)&ahi, g_ahi);
    cudaGetSymbolAddress((void**)&alo, g_alo);
    cudaGetSymbolAddress((void**)&bhi, g_bhi);
    cudaGetSymbolAddress((void**)&blo, g_blo);
    cudaGetSymbolAddress((void**)&uhi, g_uhi);
    cudaGetSymbolAddress((void**)&ulo, g_ulo);
    cudaGetSymbolAddress((void**)&hhi, g_hhi);
    cudaGetSymbolAddress((void**)&hlo, g_hlo);
    cudaGetSymbolAddress((void**)&zx_p, g_zx);

    cudaFuncSetAttribute(lstm_kernel, cudaFuncAttributeMaxDynamicSharedMemorySize, LSTM_SMEM);
    cudaFuncSetAttribute(mma_gemm_kernel<false>, cudaFuncAttributeMaxDynamicSharedMemorySize, MM_SMEM);
    cudaFuncSetAttribute(mma_gemm_kernel<true>,  cudaFuncAttributeMaxDynamicSharedMemorySize, MM_SMEM);

    reset_bar_kernel<<<1, 32>>>();

    // x -> (B*T, 960) bf16 hi/lo (coalesced tiled transpose)
    transpose_x_kernel<<<dim3(10, B_), 256>>>(x);

    // W0 -> (1024, 960) K-major hi/lo ; U0 -> permuted
    {
        long total = (long)G_ * K0P;
        wtrans_kernel<<<(int)((total + 255) / 256), 256>>>(W0, K0, G_, K0P);
        long tu = (long)G_ * U_;
        utrans_kernel<<<(int)((tu + 255) / 256), 256>>>(U0);
    }
    // zx = x @ W0 + b0
    mma_gemm_kernel<false><<<dim3(G_ / 128, M_ / 128), 256, MM_SMEM>>>(
        ahi, alo, bhi, blo, b0, zx_p, K0P, G_);

    // LSTM layer 0 -> hhi/hlo
    lstm_kernel<<<128, 256, LSTM_SMEM>>>(zx_p, uhi, ulo, hhi, hlo, 0);

    // W1 -> (1024, 256) K-major hi/lo ; U1 -> permuted
    {
        long total = (long)G_ * U_;
        wtrans_kernel<<<(int)((total + 255) / 256), 256>>>(W1, U_, G_, U_);
        utrans_kernel<<<(int)((total + 255) / 256), 256>>>(U1);
    }
    // zx = h0 @ W1 + b1
    mma_gemm_kernel<false><<<dim3(G_ / 128, M_ / 128), 256, MM_SMEM>>>(
        hhi, hlo, bhi, blo, b1, zx_p, U_, G_);

    // LSTM layer 1 -> hhi/hlo
    lstm_kernel<<<128, 256, LSTM_SMEM>>>(zx_p, uhi, ulo, hhi, hlo, 1);

    // Wd -> (600, 256) K-major hi/lo
    {
        long total = (long)ND * U_;
        wtrans_kernel<<<(int)((total + 255) / 256), 256>>>(Wd, U_, ND, U_);
    }
    // out = h1 @ Wd + bd, scattered to (B, N, T, 2)
    mma_gemm_kernel<true><<<dim3((ND + 127) / 128, M_ / 128), 256, MM_SMEM>>>(
        hhi, hlo, bhi, blo, bd, out, U_, ND);
}